// round 9
// baseline (speedup 1.0000x reference)
#include <cuda_runtime.h>
#include <cuda_bf16.h>
#include <cstdint>

// u_quant_weight_linear: out[o,i] = clip(rint(w[o,i]/s), -qmax, qmax) * s
//   s = max(alh[o], 1e-5); b = rint(clip(|bit[o]|,1,6)); qmax = max(2^(b-1)-1,1)
//
// R9: extend R8's winning lever (256-bit ld/st halved instruction count and
// broke the 6.05 TB/s plateau). Batch 8 x LDG.256 = 256B front-batched per
// thread, deepest in-thread load window yet; lowest instr count per byte.
// Total vec8 = 4096*1376 = 5636096 = 2752 * 2048: 2752 blocks x 256 thr x 8,
// zero tail. 1376 % 32 == 0 -> row index warp-uniform (const-div -> IMAD.HI).
// ~80 regs -> 3 blocks/SM (37.5% occ) is acceptable: R2 showed low-occ +
// deep MLP sustains BW; issue was only 45.5% at R8.

#define VEC8_PER_ROW 1376u
#define NTHR         256
#define BATCH        8
#define CHUNK        (NTHR * BATCH)          // 2048 vec8
#define NBLK         2752                     // 2752*2048 = 5636096 exactly

struct f8 { float4 a, b; };

__device__ __forceinline__ f8 ldg256_cs(const float* p)
{
    f8 r;
    asm volatile("ld.global.cs.v8.f32 {%0,%1,%2,%3,%4,%5,%6,%7}, [%8];"
                 : "=f"(r.a.x), "=f"(r.a.y), "=f"(r.a.z), "=f"(r.a.w),
                   "=f"(r.b.x), "=f"(r.b.y), "=f"(r.b.z), "=f"(r.b.w)
                 : "l"(p));
    return r;
}

__device__ __forceinline__ void stg256_cs(float* p, f8 v)
{
    asm volatile("st.global.cs.v8.f32 [%0], {%1,%2,%3,%4,%5,%6,%7,%8};"
                 :: "l"(p),
                    "f"(v.a.x), "f"(v.a.y), "f"(v.a.z), "f"(v.a.w),
                    "f"(v.b.x), "f"(v.b.y), "f"(v.b.z), "f"(v.b.w)
                 : "memory");
}

__device__ __forceinline__ void row_params(unsigned idx8,
                                           const float* __restrict__ alh,
                                           const float* __restrict__ bit,
                                           float& s, float& qmax)
{
    const unsigned r = idx8 / VEC8_PER_ROW;   // warp-uniform; const-div
    s = fmaxf(alh[r], 1e-5f);
    const float b = rintf(fminf(fmaxf(fabsf(bit[r]), 1.0f), 6.0f));
    qmax = fmaxf(exp2f(b - 1.0f) - 1.0f, 1.0f);
}

__device__ __forceinline__ float qf(float x, float s, float qmin, float qmax)
{
    // True IEEE divide: rint decisions must match the reference exactly.
    return fminf(fmaxf(rintf(x / s), qmin), qmax) * s;
}

__device__ __forceinline__ f8 quant8(f8 v, float s, float qmax)
{
    const float qmin = -qmax;
    v.a.x = qf(v.a.x, s, qmin, qmax);  v.a.y = qf(v.a.y, s, qmin, qmax);
    v.a.z = qf(v.a.z, s, qmin, qmax);  v.a.w = qf(v.a.w, s, qmin, qmax);
    v.b.x = qf(v.b.x, s, qmin, qmax);  v.b.y = qf(v.b.y, s, qmin, qmax);
    v.b.z = qf(v.b.z, s, qmin, qmax);  v.b.w = qf(v.b.w, s, qmin, qmax);
    return v;
}

__global__ __launch_bounds__(NTHR, 3)
void fake_quant_kernel(const float* __restrict__ w,
                       const float* __restrict__ alh,
                       const float* __restrict__ bit,
                       float* __restrict__ out)
{
    const unsigned base = blockIdx.x * CHUNK + threadIdx.x;   // vec8 index

    // Front-batch all 8 256-bit loads: 256B in flight per thread.
    f8 v[BATCH];
    #pragma unroll
    for (int i = 0; i < BATCH; i++)
        v[i] = ldg256_cs(w + (size_t)(base + i * NTHR) * 8u);

    #pragma unroll
    for (int i = 0; i < BATCH; i++) {
        const unsigned idx8 = base + i * NTHR;
        float s, qmax;
        row_params(idx8, alh, bit, s, qmax);
        stg256_cs(out + (size_t)idx8 * 8u, quant8(v[i], s, qmax));
    }
}

extern "C" void kernel_launch(void* const* d_in, const int* in_sizes, int n_in,
                              void* d_out, int out_size)
{
    const float* w   = (const float*)d_in[0];  // weight [4096, 11008]
    const float* alh = (const float*)d_in[1];  // [4096, 1]
    const float* bit = (const float*)d_in[2];  // [4096, 1]
    float* out = (float*)d_out;

    fake_quant_kernel<<<NBLK, NTHR>>>(w, alh, bit, out);
}

// round 10
// speedup vs baseline: 1.0229x; 1.0229x over previous
#include <cuda_runtime.h>
#include <cuda_bf16.h>
#include <cstdint>

// u_quant_weight_linear: out[o,i] = clip(rint(w[o,i]/s), -qmax, qmax) * s
//   s = max(alh[o], 1e-5); b = rint(clip(|bit[o]|,1,6)); qmax = max(2^(b-1)-1,1)
//
// R10 = R8 (best: 256-bit ld/st, batch 4, 5504x256, 6.22 TB/s @ 53% occ)
//       + two-row param trick to cut regs 48 -> ~40 -> 6 blocks/SM.
// Chunk = 1024 vec8 < 1376 vec8/row => block spans at most 2 rows:
// one udiv per block, per-item select by idx8 >= boundary.
// Occupancy floor established (R9: 33% occ -> 69.6% DRAM); this raises occ
// while keeping R8's instruction-count win.

#define VEC8_PER_ROW 1376u
#define LAST_ROW     4095u
#define NTHR         256
#define BATCH        4
#define CHUNK        (NTHR * BATCH)          // 1024 vec8
#define NBLK         5504                     // 5504*1024 = 5636096 exactly

struct f8 { float4 a, b; };

__device__ __forceinline__ f8 ldg256_cs(const float* p)
{
    f8 r;
    asm volatile("ld.global.cs.v8.f32 {%0,%1,%2,%3,%4,%5,%6,%7}, [%8];"
                 : "=f"(r.a.x), "=f"(r.a.y), "=f"(r.a.z), "=f"(r.a.w),
                   "=f"(r.b.x), "=f"(r.b.y), "=f"(r.b.z), "=f"(r.b.w)
                 : "l"(p));
    return r;
}

__device__ __forceinline__ void stg256_cs(float* p, f8 v)
{
    asm volatile("st.global.cs.v8.f32 [%0], {%1,%2,%3,%4,%5,%6,%7,%8};"
                 :: "l"(p),
                    "f"(v.a.x), "f"(v.a.y), "f"(v.a.z), "f"(v.a.w),
                    "f"(v.b.x), "f"(v.b.y), "f"(v.b.z), "f"(v.b.w)
                 : "memory");
}

__device__ __forceinline__ void make_params(float a, float bt,
                                            float& s, float& qmax)
{
    s = fmaxf(a, 1e-5f);
    const float b = rintf(fminf(fmaxf(fabsf(bt), 1.0f), 6.0f));
    qmax = fmaxf(exp2f(b - 1.0f) - 1.0f, 1.0f);
}

__device__ __forceinline__ float qf(float x, float s, float qmin, float qmax)
{
    // True IEEE divide: rint decisions must match the reference exactly.
    return fminf(fmaxf(rintf(x / s), qmin), qmax) * s;
}

__device__ __forceinline__ f8 quant8(f8 v, float s, float qmax)
{
    const float qmin = -qmax;
    v.a.x = qf(v.a.x, s, qmin, qmax);  v.a.y = qf(v.a.y, s, qmin, qmax);
    v.a.z = qf(v.a.z, s, qmin, qmax);  v.a.w = qf(v.a.w, s, qmin, qmax);
    v.b.x = qf(v.b.x, s, qmin, qmax);  v.b.y = qf(v.b.y, s, qmin, qmax);
    v.b.z = qf(v.b.z, s, qmin, qmax);  v.b.w = qf(v.b.w, s, qmin, qmax);
    return v;
}

__global__ __launch_bounds__(NTHR, 6)
void fake_quant_kernel(const float* __restrict__ w,
                       const float* __restrict__ alh,
                       const float* __restrict__ bit,
                       float* __restrict__ out)
{
    const unsigned blk_start = blockIdx.x * CHUNK;
    const unsigned base      = blk_start + threadIdx.x;      // vec8 index

    // Block-uniform two-row parameters (single udiv; broadcast L1 loads).
    const unsigned r0       = blk_start / VEC8_PER_ROW;
    const unsigned boundary = (r0 + 1u) * VEC8_PER_ROW;
    const unsigned r1       = min(r0 + 1u, LAST_ROW);
    float s0, q0, s1, q1;
    make_params(alh[r0], bit[r0], s0, q0);
    make_params(alh[r1], bit[r1], s1, q1);

    // Front-batch all 4 256-bit loads (128B in flight per thread).
    f8 v[BATCH];
    #pragma unroll
    for (int i = 0; i < BATCH; i++)
        v[i] = ldg256_cs(w + (size_t)(base + i * NTHR) * 8u);

    #pragma unroll
    for (int i = 0; i < BATCH; i++) {
        const unsigned idx8 = base + i * NTHR;
        const bool hi = idx8 >= boundary;                    // SEL, no udiv
        const float s    = hi ? s1 : s0;
        const float qmax = hi ? q1 : q0;
        stg256_cs(out + (size_t)idx8 * 8u, quant8(v[i], s, qmax));
    }
}

extern "C" void kernel_launch(void* const* d_in, const int* in_sizes, int n_in,
                              void* d_out, int out_size)
{
    const float* w   = (const float*)d_in[0];  // weight [4096, 11008]
    const float* alh = (const float*)d_in[1];  // [4096, 1]
    const float* bit = (const float*)d_in[2];  // [4096, 1]
    float* out = (float*)d_out;

    fake_quant_kernel<<<NBLK, NTHR>>>(w, alh, bit, out);
}

// round 11
// speedup vs baseline: 1.0584x; 1.0347x over previous
#include <cuda_runtime.h>
#include <cuda_bf16.h>
#include <cstdint>

// u_quant_weight_linear: out[o,i] = clip(rint(w[o,i]/s), -qmax, qmax) * s
//   s = max(alh[o], 1e-5); b = rint(clip(|bit[o]|,1,6)); qmax = max(2^(b-1)-1,1)
//
// FINAL (= R8, the measured optimum at 48.99us kernel / 6.22 TB/s / 78.5% DRAM):
// 256-bit global ld/st (Blackwell LDG.E.256/STG.E.256), batch 4 front-batched
// per thread (128B in flight), 5504 blocks x 256 thr, zero tail
// (4096*1376 vec8 = 5504*1024 exactly). launch_bounds(256,5) -> 48 regs:
// enough to hold the full load batch in registers (the critical property —
// capping regs tighter forces ptxas to serialize the loads, R6/R10), at
// 5 blocks/SM = 160KB genuinely-outstanding bytes/SM, the max of the
// constraint surface mapped over R2-R10:
//   - deeper batch (R9: 256B/thr, 33% occ)  -> 5.5 TB/s (occupancy floor)
//   - higher occ   (R10: 40 regs, 63% occ)  -> 5.6 TB/s (load serialization)
//   - 128-bit path (R5: same shape)          -> 6.05 TB/s (2x LSU instr cost)
//   - bulk-async   (R7: TMA pipeline)        -> 4.9 TB/s (epilogue-paced)
// Per-item row index via const-div (warp-uniform: 1376 % 32 == 0; alh/bit
// loads broadcast). True IEEE divide in the quantizer: rint decisions match
// the reference bit-for-bit (rel_err 0.0 across all benches).

#define VEC8_PER_ROW 1376u
#define NTHR         256
#define BATCH        4
#define CHUNK        (NTHR * BATCH)          // 1024 vec8
#define NBLK         5504                     // 5504*1024 = 5636096 exactly

struct f8 { float4 a, b; };

__device__ __forceinline__ f8 ldg256_cs(const float* p)
{
    f8 r;
    asm volatile("ld.global.cs.v8.f32 {%0,%1,%2,%3,%4,%5,%6,%7}, [%8];"
                 : "=f"(r.a.x), "=f"(r.a.y), "=f"(r.a.z), "=f"(r.a.w),
                   "=f"(r.b.x), "=f"(r.b.y), "=f"(r.b.z), "=f"(r.b.w)
                 : "l"(p));
    return r;
}

__device__ __forceinline__ void stg256_cs(float* p, f8 v)
{
    asm volatile("st.global.cs.v8.f32 [%0], {%1,%2,%3,%4,%5,%6,%7,%8};"
                 :: "l"(p),
                    "f"(v.a.x), "f"(v.a.y), "f"(v.a.z), "f"(v.a.w),
                    "f"(v.b.x), "f"(v.b.y), "f"(v.b.z), "f"(v.b.w)
                 : "memory");
}

__device__ __forceinline__ void row_params(unsigned idx8,
                                           const float* __restrict__ alh,
                                           const float* __restrict__ bit,
                                           float& s, float& qmax)
{
    const unsigned r = idx8 / VEC8_PER_ROW;   // warp-uniform; const-div
    s = fmaxf(alh[r], 1e-5f);
    const float b = rintf(fminf(fmaxf(fabsf(bit[r]), 1.0f), 6.0f));
    qmax = fmaxf(exp2f(b - 1.0f) - 1.0f, 1.0f);
}

__device__ __forceinline__ float qf(float x, float s, float qmin, float qmax)
{
    // True IEEE divide: rint decisions must match the reference exactly.
    return fminf(fmaxf(rintf(x / s), qmin), qmax) * s;
}

__device__ __forceinline__ f8 quant8(f8 v, float s, float qmax)
{
    const float qmin = -qmax;
    v.a.x = qf(v.a.x, s, qmin, qmax);  v.a.y = qf(v.a.y, s, qmin, qmax);
    v.a.z = qf(v.a.z, s, qmin, qmax);  v.a.w = qf(v.a.w, s, qmin, qmax);
    v.b.x = qf(v.b.x, s, qmin, qmax);  v.b.y = qf(v.b.y, s, qmin, qmax);
    v.b.z = qf(v.b.z, s, qmin, qmax);  v.b.w = qf(v.b.w, s, qmin, qmax);
    return v;
}

__global__ __launch_bounds__(NTHR, 5)
void fake_quant_kernel(const float* __restrict__ w,
                       const float* __restrict__ alh,
                       const float* __restrict__ bit,
                       float* __restrict__ out)
{
    const unsigned base = blockIdx.x * CHUNK + threadIdx.x;   // vec8 index

    // Front-batch all 4 256-bit loads: 128B genuinely in flight per thread.
    f8 v[BATCH];
    #pragma unroll
    for (int i = 0; i < BATCH; i++)
        v[i] = ldg256_cs(w + (size_t)(base + i * NTHR) * 8u);

    #pragma unroll
    for (int i = 0; i < BATCH; i++) {
        const unsigned idx8 = base + i * NTHR;
        float s, qmax;
        row_params(idx8, alh, bit, s, qmax);
        stg256_cs(out + (size_t)idx8 * 8u, quant8(v[i], s, qmax));
    }
}

extern "C" void kernel_launch(void* const* d_in, const int* in_sizes, int n_in,
                              void* d_out, int out_size)
{
    const float* w   = (const float*)d_in[0];  // weight [4096, 11008]
    const float* alh = (const float*)d_in[1];  // [4096, 1]
    const float* bit = (const float*)d_in[2];  // [4096, 1]
    float* out = (float*)d_out;

    fake_quant_kernel<<<NBLK, NTHR>>>(w, alh, bit, out);
}